// round 6
// baseline (speedup 1.0000x reference)
#include <cuda_runtime.h>
#include <math.h>
#include <stdint.h>

typedef unsigned long long ull;

#define T_  256
#define B_  256
#define H_  512
#define G3  1536

// ---------------- scratch (device globals: allocation-free rule) --------------
__device__ float g_gi[(long long)T_ * B_ * G3];      // input projections
__device__ float g_outs[(long long)T_ * B_ * H_];    // pre-LN hidden states
__device__ float g_h2[2][B_ * H_ * 2];               // [pingpong][(r*512+k)*2 + {hi,lo}]
__device__ float g_w2[G3 * H_ * 2];                  // W_hh interleaved {hi,lo}

// ---------------- packed f32x2 helpers (gi GEMM) ------------------------------
__device__ __forceinline__ ull pk(float lo, float hi) {
    ull r; asm("mov.b64 %0, {%1, %2};" : "=l"(r) : "f"(lo), "f"(hi)); return r;
}
__device__ __forceinline__ void upk(ull v, float& lo, float& hi) {
    asm("mov.b64 {%0, %1}, %2;" : "=f"(lo), "=f"(hi) : "l"(v));
}
__device__ __forceinline__ void ffma2(ull& d, ull a, ull b) {
    asm("fma.rn.f32x2 %0, %1, %2, %0;" : "+l"(d) : "l"(a), "l"(b));
}

// ---------------- cp.async helpers -------------------------------------------
__device__ __forceinline__ unsigned smaddr(const void* p) {
    return (unsigned)__cvta_generic_to_shared(p);
}
__device__ __forceinline__ void cpasync16(unsigned dst, const void* src) {
    asm volatile("cp.async.cg.shared.global [%0], [%1], 16;" :: "r"(dst), "l"(src));
}
__device__ __forceinline__ void cp_commit() { asm volatile("cp.async.commit_group;"); }
template<int N> __device__ __forceinline__ void cp_wait() {
    asm volatile("cp.async.wait_group %0;" :: "n"(N));
}

// ---------------- mma.sync tf32 (plain sm_100 path) ---------------------------
__device__ __forceinline__ void mma8(float* c, const uint32_t* a, const uint32_t* b) {
    asm volatile(
        "mma.sync.aligned.m16n8k8.row.col.f32.tf32.tf32.f32 "
        "{%0,%1,%2,%3}, {%4,%5,%6,%7}, {%8,%9}, {%0,%1,%2,%3};"
        : "+f"(c[0]), "+f"(c[1]), "+f"(c[2]), "+f"(c[3])
        : "r"(a[0]), "r"(a[1]), "r"(a[2]), "r"(a[3]), "r"(b[0]), "r"(b[1]));
}
__device__ __forceinline__ float tf32_rn(float v) {
    uint32_t u; asm("cvt.rn.tf32.f32 %0, %1;" : "=r"(u) : "f"(v));
    return __uint_as_float(u);
}

// =============================================================================
// Preprocessing: split into tf32 hi + fp32 residual lo, interleaved {hi,lo}
// =============================================================================
__global__ void __launch_bounds__(256) split_whh_kernel(const float* __restrict__ Whh) {
    int i = blockIdx.x * 256 + threadIdx.x;
    float w = Whh[i];
    float hi = tf32_rn(w);
    ((float2*)g_w2)[i] = make_float2(hi, w - hi);
}
__global__ void __launch_bounds__(256) split_h0_kernel(const float* __restrict__ rnn) {
    int i = blockIdx.x * 256 + threadIdx.x;
    float v = rnn[i];
    float hi = tf32_rn(v);
    ((float2*)g_h2[0])[i] = make_float2(hi, v - hi);
}

// =============================================================================
// Kernel 1: gi = x @ W_ih^T + b_ih   (FFMA2 path, unchanged — proven)
// =============================================================================
__global__ void __launch_bounds__(256) gemm_gi_kernel(
    const float* __restrict__ X, const float* __restrict__ Wih, const float* __restrict__ bih)
{
    __shared__ float As[16][132];
    __shared__ float Bs[16][132];

    const int tid  = threadIdx.x;
    const int m0   = blockIdx.y * 128;
    const int n0   = blockIdx.x * 128;
    const int trow = tid >> 4;
    const int tcol = tid & 15;

    ull acc[4][8];
    #pragma unroll
    for (int p = 0; p < 4; p++)
        #pragma unroll
        for (int j = 0; j < 8; j++) acc[p][j] = 0ull;

    for (int kb = 0; kb < 512; kb += 16) {
        __syncthreads();
        #pragma unroll
        for (int l = 0; l < 2; l++) {
            int idx = tid + l * 256;
            int r   = idx >> 2;
            int c4  = idx & 3;
            float4 a = *(const float4*)&X[(long long)(m0 + r) * 512 + kb + c4 * 4];
            As[c4 * 4 + 0][r] = a.x; As[c4 * 4 + 1][r] = a.y;
            As[c4 * 4 + 2][r] = a.z; As[c4 * 4 + 3][r] = a.w;
            float4 b = *(const float4*)&Wih[(long long)(n0 + r) * 512 + kb + c4 * 4];
            Bs[c4 * 4 + 0][r] = b.x; Bs[c4 * 4 + 1][r] = b.y;
            Bs[c4 * 4 + 2][r] = b.z; Bs[c4 * 4 + 3][r] = b.w;
        }
        __syncthreads();
        #pragma unroll
        for (int kk = 0; kk < 16; kk++) {
            ulonglong2 a01 = *(const ulonglong2*)&As[kk][trow * 8];
            ulonglong2 a23 = *(const ulonglong2*)&As[kk][trow * 8 + 4];
            float4 b0 = *(const float4*)&Bs[kk][tcol * 8];
            float4 b1 = *(const float4*)&Bs[kk][tcol * 8 + 4];
            ull a2[4] = { a01.x, a01.y, a23.x, a23.y };
            float bv[8] = { b0.x, b0.y, b0.z, b0.w, b1.x, b1.y, b1.z, b1.w };
            #pragma unroll
            for (int j = 0; j < 8; j++) {
                ull b2 = pk(bv[j], bv[j]);
                #pragma unroll
                for (int p = 0; p < 4; p++) ffma2(acc[p][j], a2[p], b2);
            }
        }
    }

    float bias[8];
    #pragma unroll
    for (int j = 0; j < 8; j++) bias[j] = bih[n0 + tcol * 8 + j];

    #pragma unroll
    for (int p = 0; p < 4; p++) {
        float lo[8], hi[8];
        #pragma unroll
        for (int j = 0; j < 8; j++) upk(acc[p][j], lo[j], hi[j]);
        int mA = m0 + trow * 8 + 2 * p;
        int mB = mA + 1;
        float4 vA0 = { lo[0] + bias[0], lo[1] + bias[1], lo[2] + bias[2], lo[3] + bias[3] };
        float4 vA1 = { lo[4] + bias[4], lo[5] + bias[5], lo[6] + bias[6], lo[7] + bias[7] };
        float4 vB0 = { hi[0] + bias[0], hi[1] + bias[1], hi[2] + bias[2], hi[3] + bias[3] };
        float4 vB1 = { hi[4] + bias[4], hi[5] + bias[5], hi[6] + bias[6], hi[7] + bias[7] };
        float* oA = &g_gi[(long long)mA * G3 + n0 + tcol * 8];
        float* oB = &g_gi[(long long)mB * G3 + n0 + tcol * 8];
        *(float4*)(oA)     = vA0;  *(float4*)(oA + 4) = vA1;
        *(float4*)(oB)     = vB0;  *(float4*)(oB + 4) = vB1;
    }
}

// =============================================================================
// Kernel 2 (v4): GRU timestep via mma.sync 3xTF32.
//  Per CTA: D[64 rows x 48 cols] (16 j x 3 gates); grid (32 j, 4 m) = 128 CTAs.
//  K chunks of 32, 3-stage cp.async ring, {hi,lo} interleaved operands so each
//  LDS.64 fetches both split halves.  Warp grid 4(M) x 2(N): warp = 16 x 24.
//  Gate epilogue via SMEM D-exchange, fused gates, writes h + next {hi,lo}.
// =============================================================================
#define AW 72                        // words per A row (32k x 2, padded)
#define STG_WORDS (64 * AW + 48 * AW)   // 8064 words per stage
#define STEP_SMEM (3 * STG_WORDS * 4)   // 96768 bytes
#define DW 52                        // D exchange row stride (words)

__global__ void __launch_bounds__(256, 1) gru_step_mma(
    int t,
    const float* __restrict__ rnn,     // [B,H] initial hidden
    const float* __restrict__ masks,   // [T,B]
    const float* __restrict__ bhh)     // [3H]
{
    extern __shared__ __align__(16) float sm[];
    const int tid  = threadIdx.x;
    const int wid  = tid >> 5;
    const int lane = tid & 31;
    const int grp  = lane >> 2;      // 0..7
    const int qk   = lane & 3;       // 0..3
    const int j0   = blockIdx.x * 16;
    const int m0   = blockIdx.y * 64;

    const float* __restrict__ Ah = g_h2[t & 1];

    auto stage = [&](int c) {
        const int s = c % 3;
        float* As_ = sm + s * STG_WORDS;
        float* Bs_ = As_ + 64 * AW;
        const int kb = c * 32;
        unsigned abase = smaddr(As_), bbase = smaddr(Bs_);
        #pragma unroll
        for (int q = 0; q < 4; q++) {                 // A: 64 rows x 16 chunks
            int idx = q * 256 + tid;
            int r = idx >> 4, cc = idx & 15;
            cpasync16(abase + (unsigned)(r * AW + cc * 4) * 4,
                      Ah + ((long long)(m0 + r) * 512 + kb + cc * 2) * 2);
        }
        #pragma unroll
        for (int q = 0; q < 3; q++) {                 // B: 48 rows x 16 chunks
            int idx = q * 256 + tid;
            int r2 = idx >> 4, cc = idx & 15;
            int g = r2 >> 4, jj = r2 & 15;
            cpasync16(bbase + (unsigned)(r2 * AW + cc * 4) * 4,
                      g_w2 + ((long long)(g * 512 + j0 + jj) * 512 + kb + cc * 2) * 2);
        }
    };

    float acc[3][4];
    #pragma unroll
    for (int j = 0; j < 3; j++)
        #pragma unroll
        for (int p = 0; p < 4; p++) acc[j][p] = 0.0f;

    const int mt  = wid & 3;          // M tile (16 rows each)
    const int n0w = (wid >> 2) * 24;  // N offset within 48
    const int rb  = mt * 16 + grp;

    stage(0); cp_commit();
    stage(1); cp_commit();

    for (int c = 0; c < 16; c++) {
        if (c + 2 < 16) { stage(c + 2); cp_commit(); }
        if (c < 14) cp_wait<2>(); else if (c == 14) cp_wait<1>(); else cp_wait<0>();
        __syncthreads();

        const float* As_ = sm + (c % 3) * STG_WORDS;
        const float* Bs_ = As_ + 64 * AW;

        #pragma unroll
        for (int kk = 0; kk < 4; kk++) {
            const int ko = kk * 16 + qk * 2;          // word offset of k pair
            float2 a0 = *(const float2*)&As_[rb * AW + ko];
            float2 a1 = *(const float2*)&As_[(rb + 8) * AW + ko];
            float2 a2 = *(const float2*)&As_[rb * AW + ko + 8];
            float2 a3 = *(const float2*)&As_[(rb + 8) * AW + ko + 8];
            uint32_t ahf[4] = { __float_as_uint(a0.x), __float_as_uint(a1.x),
                                __float_as_uint(a2.x), __float_as_uint(a3.x) };
            uint32_t alf[4] = { __float_as_uint(a0.y), __float_as_uint(a1.y),
                                __float_as_uint(a2.y), __float_as_uint(a3.y) };
            #pragma unroll
            for (int j = 0; j < 3; j++) {
                const int nb = n0w + j * 8 + grp;
                float2 b0 = *(const float2*)&Bs_[nb * AW + ko];
                float2 b1 = *(const float2*)&Bs_[nb * AW + ko + 8];
                uint32_t bhf[2] = { __float_as_uint(b0.x), __float_as_uint(b1.x) };
                uint32_t blf[2] = { __float_as_uint(b0.y), __float_as_uint(b1.y) };
                mma8(acc[j], ahf, bhf);
                mma8(acc[j], ahf, blf);
                mma8(acc[j], alf, bhf);
            }
        }
        __syncthreads();
    }

    // ---- D exchange through SMEM (gates live in different warps' tiles) ----
    float* Ds = sm;   // 64 x DW, reuses stage memory (post-barrier)
    #pragma unroll
    for (int j = 0; j < 3; j++) {
        const int cb = n0w + j * 8 + qk * 2;
        *(float2*)&Ds[(mt * 16 + grp) * DW + cb]     = make_float2(acc[j][0], acc[j][1]);
        *(float2*)&Ds[(mt * 16 + grp + 8) * DW + cb] = make_float2(acc[j][2], acc[j][3]);
    }
    __syncthreads();

    // ---- fused gates epilogue: 64 rows x 16 jj = 1024 elems, 4 per thread ----
    const float* prev = (t == 0) ? rnn : (g_outs + (long long)(t - 1) * B_ * H_);
    const float* gi_t = g_gi + (long long)t * B_ * G3;
    float*       out_t = g_outs + (long long)t * B_ * H_;
    float2*      h2w   = (float2*)g_h2[(t + 1) & 1];

    #pragma unroll
    for (int it = 0; it < 4; it++) {
        int idx = it * 256 + tid;
        int row = idx >> 4, jj = idx & 15;
        int r = m0 + row, j = j0 + jj;
        float s0 = Ds[row * DW + jj];
        float s1 = Ds[row * DW + jj + 16];
        float s2 = Ds[row * DW + jj + 32];
        float m  = __ldg(&masks[t * B_ + r]);
        float hp = __ldg(&prev[(long long)r * 512 + j]);
        float ir  = __ldg(&gi_t[(long long)r * G3 + j]);
        float iz  = __ldg(&gi_t[(long long)r * G3 + 512 + j]);
        float inn = __ldg(&gi_t[(long long)r * G3 + 1024 + j]);
        float br = __ldg(&bhh[j]);
        float bz = __ldg(&bhh[512 + j]);
        float bn = __ldg(&bhh[1024 + j]);

        const float ghr = m * s0 + br;
        const float ghz = m * s1 + bz;
        const float ghn = m * s2 + bn;
        const float rr = 1.0f / (1.0f + __expf(-(ir + ghr)));
        const float zz = 1.0f / (1.0f + __expf(-(iz + ghz)));
        const float xv = inn + rr * ghn;
        const float e2 = __expf(-2.0f * fabsf(xv));
        const float th = (1.0f - e2) / (1.0f + e2);
        const float nn = copysignf(th, xv);
        const float hnew = (1.0f - zz) * nn + zz * (m * hp);

        out_t[(long long)r * 512 + j] = hnew;
        float hi = tf32_rn(hnew);
        h2w[(long long)r * 512 + j] = make_float2(hi, hnew - hi);
    }
}

// =============================================================================
// Kernel 3: LayerNorm over g_outs -> y in d_out; also copy hT.
// =============================================================================
__global__ void __launch_bounds__(256) ln_kernel(
    const float* __restrict__ lnw,
    const float* __restrict__ lnb,
    float* __restrict__ out,
    int write_hT)
{
    const int row  = blockIdx.x * 8 + (threadIdx.x >> 5);
    const int lane = threadIdx.x & 31;
    const float4* p4 = (const float4*)(g_outs + (long long)row * 512);

    float4 v[4];
    float s = 0.0f, sq = 0.0f;
    #pragma unroll
    for (int i = 0; i < 4; i++) {
        v[i] = p4[lane + 32 * i];
        s += v[i].x + v[i].y + v[i].z + v[i].w;
        sq = fmaf(v[i].x, v[i].x, sq);
        sq = fmaf(v[i].y, v[i].y, sq);
        sq = fmaf(v[i].z, v[i].z, sq);
        sq = fmaf(v[i].w, v[i].w, sq);
    }
    #pragma unroll
    for (int off = 16; off > 0; off >>= 1) {
        s  += __shfl_xor_sync(0xFFFFFFFFu, s,  off);
        sq += __shfl_xor_sync(0xFFFFFFFFu, sq, off);
    }
    const float mean = s * (1.0f / 512.0f);
    const float var  = sq * (1.0f / 512.0f) - mean * mean;
    const float rstd = rsqrtf(var + 1e-5f);

    float4* o4 = (float4*)out + (long long)row * 128;
    const float4* w4 = (const float4*)lnw;
    const float4* b4 = (const float4*)lnb;
    const bool isLast = (row >= 255 * 256) && write_hT;
    float4* h4 = (float4*)(out + (long long)T_ * B_ * H_) + (long long)(row - 255 * 256) * 128;

    #pragma unroll
    for (int i = 0; i < 4; i++) {
        int idx = lane + 32 * i;
        float4 w = w4[idx], b = b4[idx];
        float4 y;
        y.x = (v[i].x - mean) * rstd * w.x + b.x;
        y.y = (v[i].y - mean) * rstd * w.y + b.y;
        y.z = (v[i].z - mean) * rstd * w.z + b.z;
        y.w = (v[i].w - mean) * rstd * w.w + b.w;
        o4[idx] = y;
        if (isLast) h4[idx] = v[i];
    }
}

// =============================================================================
extern "C" void kernel_launch(void* const* d_in, const int* in_sizes, int n_in,
                              void* d_out, int out_size)
{
    const float* x     = (const float*)d_in[0];  // (T,B,I)
    const float* rnn   = (const float*)d_in[1];  // (1,B,H)
    const float* masks = (const float*)d_in[2];  // (T,B,1)
    const float* Wih   = (const float*)d_in[3];  // (3H,I)
    const float* Whh   = (const float*)d_in[4];  // (3H,H)
    const float* bih   = (const float*)d_in[5];  // (3H)
    const float* bhh   = (const float*)d_in[6];  // (3H)
    const float* lnw   = (const float*)d_in[7];  // (H)
    const float* lnb   = (const float*)d_in[8];  // (H)
    float* out = (float*)d_out;

    (void)in_sizes; (void)n_in;

    cudaFuncSetAttribute(gru_step_mma,
                         cudaFuncAttributeMaxDynamicSharedMemorySize, STEP_SMEM);

    // 0) splits for 3xTF32
    split_whh_kernel<<<(G3 * H_) / 256, 256>>>(Whh);
    split_h0_kernel<<<(B_ * H_) / 256, 256>>>(rnn);

    // 1) input projections for all timesteps
    gemm_gi_kernel<<<dim3(12, 512), 256>>>(x, Wih, bih);

    // 2) sequential recurrence on tensor cores (mma.sync tf32)
    for (int t = 0; t < T_; t++)
        gru_step_mma<<<dim3(32, 4), 256, STEP_SMEM>>>(t, rnn, masks, bhh);

    // 3) LayerNorm + hT copy
    const int write_hT = (out_size >= T_ * B_ * H_ + B_ * H_) ? 1 : 0;
    ln_kernel<<<(T_ * B_) / 8, 256>>>(lnw, lnb, out, write_hT);
}